// round 1
// baseline (speedup 1.0000x reference)
#include <cuda_runtime.h>

#define CELL_N 76
#define DRUG_N 764
#define TOT_N  840
#define BATCH  4096
#define NPROT  15970

// ---------------- scratch (device globals; no allocs allowed) ----------------
__device__ float g_pool1[TOT_N * 4 * 64 * 64];   // after conv1+relu+pool
__device__ float g_pool2[TOT_N * 8 * 32 * 32];   // after conv2+relu+pool
__device__ float g_item [TOT_N * 64];            // FC out, standardized in place
__device__ float g_inter[TOT_N * 128];           // interact output
__device__ float g_emb  [TOT_N * 64];            // agg output (cell 0..75, drug 76..839)
__device__ float g_normsq[TOT_N];                // per-row |emb|^2
__device__ float g_U    [CELL_N * 128];          // comb_w^T @ cell_emb[c]
__device__ float g_tablesq[NPROT];               // per-protein-row |.|^2
__device__ float g_part [32];                    // item_reg block partials (deterministic)

// ---------------- per-protein squared norms ----------------
__global__ void k_tablesq(const float* __restrict__ table) {
    int warp = (blockIdx.x * blockDim.x + threadIdx.x) >> 5;
    int lane = threadIdx.x & 31;
    if (warp >= NPROT) return;
    const float* r = table + warp * 64;
    float a = r[lane], b = r[lane + 32];
    float s = a * a + b * b;
    #pragma unroll
    for (int o = 16; o; o >>= 1) s += __shfl_down_sync(0xffffffffu, s, o);
    if (lane == 0) g_tablesq[warp] = s;
}

// ---------------- conv1 (1->4, 3x3 SAME) + relu + 2x2 maxpool ----------------
// grid = N*2 (half image rows per block), block = 256
__global__ void k_conv1(const float* __restrict__ x, const float* __restrict__ w,
                        const float* __restrict__ b, int obase) {
    int n = blockIdx.x >> 1, half = blockIdx.x & 1;
    __shared__ float tile[66 * 130];
    __shared__ float ws[36];
    __shared__ float bs[4];
    int tid = threadIdx.x;
    if (tid < 36) ws[tid] = w[tid];
    if (tid < 4)  bs[tid] = b[tid];
    int row0 = half * 64 - 1;
    const float* xn = x + n * 128 * 128;
    for (int idx = tid; idx < 66 * 130; idx += 256) {
        int r = idx / 130, c = idx - r * 130;
        int y = row0 + r, xx = c - 1;
        tile[idx] = (y >= 0 && y < 128 && (unsigned)xx < 128u) ? xn[y * 128 + xx] : 0.f;
    }
    __syncthreads();
    // outputs: oc in [0,4), oy in [0,32) (pool rows within half), ox in [0,64)
    for (int o = tid; o < 4 * 32 * 64; o += 256) {
        int oc = o >> 11, rem = o & 2047, oy = rem >> 6, ox = rem & 63;
        float m = -1e30f;
        #pragma unroll
        for (int sy = 0; sy < 2; sy++)
        #pragma unroll
        for (int sx = 0; sx < 2; sx++) {
            float v = bs[oc];
            #pragma unroll
            for (int dy = 0; dy < 3; dy++)
            #pragma unroll
            for (int dx = 0; dx < 3; dx++)
                v += tile[(2 * oy + sy + dy) * 130 + 2 * ox + sx + dx] * ws[oc * 9 + dy * 3 + dx];
            m = fmaxf(m, v);
        }
        g_pool1[obase + ((n * 4 + oc) * 64 + half * 32 + oy) * 64 + ox] = fmaxf(m, 0.f);
    }
}

// ---------------- conv2 (4->8, 3x3 SAME) + relu + 2x2 maxpool ----------------
// grid = TOT_N*2, block = 256
__global__ void k_conv2(const float* __restrict__ w, const float* __restrict__ b) {
    int n = blockIdx.x >> 1, half = blockIdx.x & 1;
    __shared__ float tile[4 * 34 * 66];   // 4ch x (32+2) x (64+2)
    __shared__ float ws[288];
    __shared__ float bs[8];
    int tid = threadIdx.x;
    for (int i = tid; i < 288; i += 256) ws[i] = w[i];
    if (tid < 8) bs[tid] = b[tid];
    int row0 = half * 32 - 1;
    for (int idx = tid; idx < 4 * 34 * 66; idx += 256) {
        int c = idx / (34 * 66), rem = idx - c * 34 * 66;
        int r = rem / 66, cc = rem - r * 66;
        int y = row0 + r, xx = cc - 1;
        tile[idx] = (y >= 0 && y < 64 && (unsigned)xx < 64u)
                  ? g_pool1[((n * 4 + c) * 64 + y) * 64 + xx] : 0.f;
    }
    __syncthreads();
    // outputs: oc in [0,8), oy in [0,16), ox in [0,32)
    for (int o = tid; o < 8 * 16 * 32; o += 256) {
        int oc = o >> 9, rem = o & 511, oy = rem >> 5, ox = rem & 31;
        float m = -1e30f;
        #pragma unroll
        for (int sy = 0; sy < 2; sy++)
        #pragma unroll
        for (int sx = 0; sx < 2; sx++) {
            float v = bs[oc];
            #pragma unroll
            for (int c = 0; c < 4; c++)
            #pragma unroll
            for (int dy = 0; dy < 3; dy++)
            #pragma unroll
            for (int dx = 0; dx < 3; dx++)
                v += tile[c * 34 * 66 + (2 * oy + sy + dy) * 66 + 2 * ox + sx + dx]
                   * ws[((oc * 4 + c) * 3 + dy) * 3 + dx];
            m = fmaxf(m, v);
        }
        g_pool2[((n * 8 + oc) * 32 + half * 16 + oy) * 32 + ox] = fmaxf(m, 0.f);
    }
}

// ---------------- FC: item[n,j] = pool2[n,:] . W[j,:] + b[j] ----------------
// grid = TOT_N, block = 256 (8 warps, 8 outputs per warp)
__global__ void k_fc(const float* __restrict__ W, const float* __restrict__ b) {
    int n = blockIdx.x;
    __shared__ float xs[8192];
    int tid = threadIdx.x;
    const float* xin = g_pool2 + n * 8192;
    for (int i = tid; i < 8192; i += 256) xs[i] = xin[i];
    __syncthreads();
    int warp = tid >> 5, lane = tid & 31;
    float acc[8] = {0, 0, 0, 0, 0, 0, 0, 0};
    const float* Wb = W + warp * 8 * 8192;
    for (int i = lane; i < 8192; i += 32) {
        float xv = xs[i];
        #pragma unroll
        for (int jj = 0; jj < 8; jj++) acc[jj] += xv * Wb[jj * 8192 + i];
    }
    #pragma unroll
    for (int jj = 0; jj < 8; jj++) {
        float s = acc[jj];
        #pragma unroll
        for (int o = 16; o; o >>= 1) s += __shfl_down_sync(0xffffffffu, s, o);
        if (lane == 0) g_item[n * 64 + warp * 8 + jj] = s + b[warp * 8 + jj];
    }
}

// ---------------- standardize per feature over a group (ddof=1) ----------------
// grid = 1, block = 256 (feature j = tid&63, slice q = tid>>6)
__global__ void k_std(int base, int N) {
    __shared__ float red[256];
    __shared__ float mv[64];
    __shared__ float sv[64];
    float* x = g_item + base;
    int tid = threadIdx.x;
    int j = tid & 63, q = tid >> 6;
    float s = 0.f;
    for (int n = q; n < N; n += 4) s += x[n * 64 + j];
    red[tid] = s;
    __syncthreads();
    if (tid < 64) mv[tid] = (red[tid] + red[tid + 64] + red[tid + 128] + red[tid + 192]) / (float)N;
    __syncthreads();
    float mean = mv[j];
    float ss = 0.f;
    for (int n = q; n < N; n += 4) { float d = x[n * 64 + j] - mean; ss += d * d; }
    __syncthreads();
    red[tid] = ss;
    __syncthreads();
    if (tid < 64) {
        float var = (red[tid] + red[tid + 64] + red[tid + 128] + red[tid + 192]) / (float)(N - 1);
        sv[tid] = rsqrtf(var);
    }
    __syncthreads();
    float inv = sv[j];
    for (int n = q; n < N; n += 4) x[n * 64 + j] = (x[n * 64 + j] - mean) * inv;
}

// ---------------- interact: attention over 128 gathered protein rows ----------------
// grid = N*2 (one block per (n, hop)), block = 128
__global__ void k_interact(const int* __restrict__ nbr, const float* __restrict__ table,
                           int item_base, int inter_base) {
    int nh = blockIdx.x;
    int n = nh >> 1, h = nh & 1;
    __shared__ float rows[128 * 65];   // padded: conflict-free both ways
    __shared__ float it[64];
    __shared__ int   idxs[128];
    __shared__ float sc[128];
    __shared__ float tmp[128];
    int tid = threadIdx.x;
    idxs[tid] = nbr[nh * 128 + tid];
    if (tid < 64) it[tid] = g_item[item_base + n * 64 + tid];
    __syncthreads();
    for (int e = tid; e < 128 * 64; e += 128) {
        int k = e >> 6, d = e & 63;
        rows[k * 65 + d] = table[idxs[k] * 64 + d];
    }
    __syncthreads();
    float s = 0.f;
    #pragma unroll 8
    for (int d = 0; d < 64; d++) s += rows[tid * 65 + d] * it[d];
    tmp[tid] = s;
    __syncthreads();
    #pragma unroll
    for (int off = 64; off; off >>= 1) {
        if (tid < off) tmp[tid] = fmaxf(tmp[tid], tmp[tid + off]);
        __syncthreads();
    }
    float mx = tmp[0];
    __syncthreads();
    float e = expf(s - mx);
    sc[tid] = e;
    tmp[tid] = e;
    __syncthreads();
    #pragma unroll
    for (int off = 64; off; off >>= 1) {
        if (tid < off) tmp[tid] += tmp[tid + off];
        __syncthreads();
    }
    float inv = 1.f / tmp[0];
    if (tid < 64) {
        float o = 0.f;
        #pragma unroll 8
        for (int k = 0; k < 128; k++) o += sc[k] * rows[k * 65 + tid];
        g_inter[inter_base + n * 128 + h * 64 + tid] = o * inv;
    }
}

// ---------------- agg: emb[n,j] = inter[n,:] . agg_w[j,:] + b[j]; also |emb|^2 ----------------
// grid = TOT_N, block = 128
__global__ void k_agg(const float* __restrict__ W, const float* __restrict__ b) {
    int n = blockIdx.x;
    __shared__ float xr[128];
    __shared__ float red[64];
    int tid = threadIdx.x;
    xr[tid] = g_inter[n * 128 + tid];
    __syncthreads();
    float e = 0.f;
    if (tid < 64) {
        float s = b[tid];
        #pragma unroll 8
        for (int t = 0; t < 128; t++) s += W[tid * 128 + t] * xr[t];
        g_emb[n * 64 + tid] = s;
        e = s * s;
    }
    if (tid < 64) red[tid] = e;
    __syncthreads();
    if (tid < 32) {
        float v = red[tid] + red[tid + 32];
        #pragma unroll
        for (int o = 16; o; o >>= 1) v += __shfl_down_sync(0xffffffffu, v, o);
        if (tid == 0) g_normsq[n] = v;
    }
}

// ---------------- U[c,t] = sum_j comb_w[j,t] * cell_emb[c,j] ----------------
// grid = CELL_N, block = 128
__global__ void k_u(const float* __restrict__ combw) {
    int c = blockIdx.x;
    __shared__ float e[64];
    int tid = threadIdx.x;
    if (tid < 64) e[tid] = g_emb[c * 64 + tid];
    __syncthreads();
    float s = 0.f;
    #pragma unroll 8
    for (int j = 0; j < 64; j++) s += combw[j * 128 + tid] * e[j];
    g_U[c * 128 + tid] = s;
}

// ---------------- per-batch score + item_reg partials (deterministic) ----------------
// grid = 32, block = 128
__global__ void k_score(const int* __restrict__ data, float* __restrict__ out) {
    int bidx = blockIdx.x * blockDim.x + threadIdx.x;
    float reg = 0.f;
    if (bidx < BATCH) {
        int c  = data[3 * bidx];
        int d1 = data[3 * bidx + 1];
        int d2 = data[3 * bidx + 2];
        const float* e1 = g_emb + (CELL_N + d1) * 64;
        const float* e2 = g_emb + (CELL_N + d2) * 64;
        const float* u  = g_U + c * 128;
        float s = 0.f;
        #pragma unroll 8
        for (int t = 0; t < 64; t++) {
            float a = e1[t], bb = e2[t];
            s += a * u[t] + bb * u[64 + t] - a * bb;
        }
        out[bidx] = s;
        reg = 0.5f * (g_normsq[c] + g_normsq[CELL_N + d1] + g_normsq[CELL_N + d2]);
    }
    __shared__ float red[128];
    red[threadIdx.x] = reg;
    __syncthreads();
    #pragma unroll
    for (int off = 64; off; off >>= 1) {
        if (threadIdx.x < off) red[threadIdx.x] += red[threadIdx.x + off];
        __syncthreads();
    }
    if (threadIdx.x == 0) g_part[blockIdx.x] = red[0];
}

// ---------------- node_reg (only batch rows 0 and 1 contribute!) + loss ----------------
// grid = 1, block = 256
__global__ void k_loss(const int* __restrict__ data, const int* __restrict__ cell_nbr,
                       const int* __restrict__ drug_nbr, float* __restrict__ out, int loss_idx) {
    __shared__ float red[256];
    int tid = threadIdx.x;
    float s = 0.f;
    // 6 sets (hop in {0,1} x {cell, drug1, drug2}) x 256 neighbor entries
    for (int e = tid; e < 1536; e += 256) {
        int set = e >> 8, off = e & 255;
        int hop = set / 3, which = set - hop * 3;
        int nodeidx = data[hop * 3 + which];
        int p = (which == 0) ? cell_nbr[nodeidx * 256 + off] : drug_nbr[nodeidx * 256 + off];
        s += g_tablesq[p];
    }
    red[tid] = s;
    __syncthreads();
    #pragma unroll
    for (int off = 128; off; off >>= 1) {
        if (tid < off) red[tid] += red[tid + off];
        __syncthreads();
    }
    if (tid == 0) {
        float item_reg = 0.f;
        #pragma unroll
        for (int i = 0; i < 32; i++) item_reg += g_part[i];
        out[loss_idx] = 1e-6f * (item_reg + 0.5f * red[0]) / (float)BATCH;
    }
}

// ---------------- launch ----------------
extern "C" void kernel_launch(void* const* d_in, const int* in_sizes, int n_in,
                              void* d_out, int out_size) {
    const int*   data     = (const int*)  d_in[0];
    const int*   cell_nbr = (const int*)  d_in[1];
    const int*   drug_nbr = (const int*)  d_in[2];
    const float* table    = (const float*)d_in[3];
    const float* cell_pre = (const float*)d_in[4];
    const float* drug_pre = (const float*)d_in[5];
    const float* c1w      = (const float*)d_in[6];
    const float* c1b      = (const float*)d_in[7];
    const float* c2w      = (const float*)d_in[8];
    const float* c2b      = (const float*)d_in[9];
    const float* ow       = (const float*)d_in[10];
    const float* ob       = (const float*)d_in[11];
    const float* aw       = (const float*)d_in[12];
    const float* ab       = (const float*)d_in[13];
    const float* cw       = (const float*)d_in[14];
    float* out = (float*)d_out;

    // per-protein squared norms (for node_reg)
    k_tablesq<<<(NPROT * 32 + 255) / 256, 256>>>(table);

    // CNN stage 1
    k_conv1<<<CELL_N * 2, 256>>>(cell_pre, c1w, c1b, 0);
    k_conv1<<<DRUG_N * 2, 256>>>(drug_pre, c1w, c1b, CELL_N * 4 * 64 * 64);
    // CNN stage 2 (all 840 images)
    k_conv2<<<TOT_N * 2, 256>>>(c2w, c2b);
    // FC
    k_fc<<<TOT_N, 256>>>(ow, ob);
    // standardize per group
    k_std<<<1, 256>>>(0, CELL_N);
    k_std<<<1, 256>>>(CELL_N * 64, DRUG_N);
    // interact
    k_interact<<<CELL_N * 2, 128>>>(cell_nbr, table, 0, 0);
    k_interact<<<DRUG_N * 2, 128>>>(drug_nbr, table, CELL_N * 64, CELL_N * 128);
    // agg + norms
    k_agg<<<TOT_N, 128>>>(aw, ab);
    // U table (cells only)
    k_u<<<CELL_N, 128>>>(cw);
    // scores + item_reg partials
    k_score<<<32, 128>>>(data, out);
    // loss
    k_loss<<<1, 256>>>(data, cell_nbr, drug_nbr, out, out_size - 1);
}

// round 2
// speedup vs baseline: 1.4486x; 1.4486x over previous
#include <cuda_runtime.h>

#define CELL_N 76
#define DRUG_N 764
#define TOT_N  840
#define BATCH  4096
#define NPROT  15970
#define KSPLIT 16
#define KCHUNK 512   // 8192 / KSPLIT

// ---------------- scratch (device globals; no allocs allowed) ----------------
__device__ float g_pool1[TOT_N * 4 * 64 * 64];   // after conv1+relu+pool
__device__ float g_pool2[TOT_N * 8 * 32 * 32];   // after conv2+relu+pool
__device__ float g_fcp  [KSPLIT * TOT_N * 64];   // FC partials (K-split)
__device__ float g_item [TOT_N * 64];            // FC out, standardized in place
__device__ float g_inter[TOT_N * 128];           // interact output
__device__ float g_emb  [TOT_N * 64];            // agg output (cell 0..75, drug 76..839)
__device__ float g_normsq[TOT_N];                // per-row |emb|^2
__device__ float g_U    [CELL_N * 128];          // comb_w^T @ cell_emb[c]
__device__ float g_tablesq[NPROT];               // per-protein-row |.|^2
__device__ float g_part [32];                    // item_reg block partials (deterministic)

// ---------------- per-protein squared norms ----------------
__global__ void k_tablesq(const float* __restrict__ table) {
    int warp = (blockIdx.x * blockDim.x + threadIdx.x) >> 5;
    int lane = threadIdx.x & 31;
    if (warp >= NPROT) return;
    const float* r = table + warp * 64;
    float a = r[lane], b = r[lane + 32];
    float s = a * a + b * b;
    #pragma unroll
    for (int o = 16; o; o >>= 1) s += __shfl_down_sync(0xffffffffu, s, o);
    if (lane == 0) g_tablesq[warp] = s;
}

// ---------------- conv1 (1->4, 3x3 SAME) + relu + 2x2 maxpool ----------------
// grid = N*2 (half image rows per block), block = 256
// Register-blocked: load 4x4 patch once (8x LDS.64), weights in registers,
// compute all 4 pre-pool positions x 4 output channels from registers.
__global__ void __launch_bounds__(256) k_conv1(
        const float* __restrict__ x, const float* __restrict__ w,
        const float* __restrict__ b, int obase) {
    int n = blockIdx.x >> 1, half = blockIdx.x & 1;
    __shared__ float tile[66 * 130];
    int tid = threadIdx.x;
    float wr[36];
    #pragma unroll
    for (int i = 0; i < 36; i++) wr[i] = w[i];
    float bb[4] = { b[0], b[1], b[2], b[3] };
    int row0 = half * 64 - 1;
    const float* xn = x + n * 128 * 128;
    for (int idx = tid; idx < 66 * 130; idx += 256) {
        int r = idx / 130, c = idx - r * 130;
        int y = row0 + r, xx = c - 1;
        tile[idx] = (y >= 0 && y < 128 && (unsigned)xx < 128u) ? xn[y * 128 + xx] : 0.f;
    }
    __syncthreads();
    #pragma unroll
    for (int i = 0; i < 8; i++) {
        int pos = tid + i * 256;            // 2048 pooled positions per half
        int oy = pos >> 6, ox = pos & 63;
        float p[4][4];
        #pragma unroll
        for (int r = 0; r < 4; r++) {
            const float2* s = (const float2*)&tile[(2 * oy + r) * 130 + 2 * ox];
            float2 a = s[0], d = s[1];
            p[r][0] = a.x; p[r][1] = a.y; p[r][2] = d.x; p[r][3] = d.y;
        }
        #pragma unroll
        for (int oc = 0; oc < 4; oc++) {
            float q00 = bb[oc], q01 = bb[oc], q10 = bb[oc], q11 = bb[oc];
            #pragma unroll
            for (int dy = 0; dy < 3; dy++)
            #pragma unroll
            for (int dx = 0; dx < 3; dx++) {
                float wv = wr[oc * 9 + dy * 3 + dx];
                q00 += p[dy    ][dx    ] * wv;
                q01 += p[dy    ][dx + 1] * wv;
                q10 += p[dy + 1][dx    ] * wv;
                q11 += p[dy + 1][dx + 1] * wv;
            }
            float m = fmaxf(fmaxf(q00, q01), fmaxf(q10, q11));
            g_pool1[obase + ((n * 4 + oc) * 64 + half * 32 + oy) * 64 + ox] = fmaxf(m, 0.f);
        }
    }
}

// ---------------- conv2 (4->8, 3x3 SAME) + relu + 2x2 maxpool ----------------
// grid = TOT_N*2, block = 256.  oc = tid>>5 fixed per thread (weights in regs),
// lanes cover 16x32 pooled positions, 16 positions per thread.
__global__ void __launch_bounds__(256) k_conv2(
        const float* __restrict__ w, const float* __restrict__ b) {
    int n = blockIdx.x >> 1, half = blockIdx.x & 1;
    __shared__ float tile[4 * 34 * 66];   // 4ch x (32+2) x (64+2)
    int tid = threadIdx.x;
    int oc = tid >> 5, lane = tid & 31;
    float wr[36];
    #pragma unroll
    for (int i = 0; i < 36; i++) wr[i] = w[oc * 36 + i];
    float bs = b[oc];
    int row0 = half * 32 - 1;
    for (int idx = tid; idx < 4 * 34 * 66; idx += 256) {
        int c = idx / (34 * 66), rem = idx - c * 34 * 66;
        int r = rem / 66, cc = rem - r * 66;
        int y = row0 + r, xx = cc - 1;
        tile[idx] = (y >= 0 && y < 64 && (unsigned)xx < 64u)
                  ? g_pool1[((n * 4 + c) * 64 + y) * 64 + xx] : 0.f;
    }
    __syncthreads();
    #pragma unroll
    for (int i = 0; i < 16; i++) {
        int pos = lane + i * 32;            // 512 pooled positions per oc
        int oy = pos >> 5, ox = pos & 31;
        float q00 = bs, q01 = bs, q10 = bs, q11 = bs;
        #pragma unroll
        for (int c = 0; c < 4; c++) {
            float p[4][4];
            #pragma unroll
            for (int r = 0; r < 4; r++) {
                const float2* s = (const float2*)&tile[c * 2244 + (2 * oy + r) * 66 + 2 * ox];
                float2 a = s[0], d = s[1];
                p[r][0] = a.x; p[r][1] = a.y; p[r][2] = d.x; p[r][3] = d.y;
            }
            #pragma unroll
            for (int dy = 0; dy < 3; dy++)
            #pragma unroll
            for (int dx = 0; dx < 3; dx++) {
                float wv = wr[c * 9 + dy * 3 + dx];
                q00 += p[dy    ][dx    ] * wv;
                q01 += p[dy    ][dx + 1] * wv;
                q10 += p[dy + 1][dx    ] * wv;
                q11 += p[dy + 1][dx + 1] * wv;
            }
        }
        float m = fmaxf(fmaxf(q00, q01), fmaxf(q10, q11));
        g_pool2[((n * 8 + oc) * 32 + half * 16 + oy) * 32 + ox] = fmaxf(m, 0.f);
    }
}

// ---------------- FC as tiled GEMM with K-split ----------------
// item[840,64] = pool2[840,8192] @ W^T[8192,64]
// grid = (27, 16): 32-row tiles x 16 K-chunks of 512. Partials to g_fcp.
__global__ void __launch_bounds__(256) k_fc(const float* __restrict__ W) {
    int m0 = blockIdx.x * 32;
    int kb = blockIdx.y;
    int k0 = kb * KCHUNK;
    __shared__ float Xs[32][64];
    __shared__ float Ws[64][68];          // padded: conflict-free float4 rows
    int tid = threadIdx.x;
    int tm = tid >> 5, tn = tid & 31;     // thread micro-tile: 4 m-rows x 2 n-cols
    float acc[4][2] = {};
    for (int kt = 0; kt < KCHUNK; kt += 64) {
        #pragma unroll
        for (int i = 0; i < 8; i++) {
            int idx = tid + i * 256;
            int r = idx >> 6, c = idx & 63;
            int m = m0 + r;
            Xs[r][c] = (m < TOT_N) ? g_pool2[m * 8192 + k0 + kt + c] : 0.f;
        }
        #pragma unroll
        for (int i = 0; i < 16; i++) {
            int idx = tid + i * 256;
            int j = idx >> 6, c = idx & 63;
            Ws[j][c] = W[j * 8192 + k0 + kt + c];
        }
        __syncthreads();
        #pragma unroll
        for (int kk = 0; kk < 64; kk += 4) {
            float4 w0 = *(const float4*)&Ws[tn     ][kk];
            float4 w1 = *(const float4*)&Ws[tn + 32][kk];
            #pragma unroll
            for (int r = 0; r < 4; r++) {
                float4 xv = *(const float4*)&Xs[tm * 4 + r][kk];
                acc[r][0] += xv.x * w0.x + xv.y * w0.y + xv.z * w0.z + xv.w * w0.w;
                acc[r][1] += xv.x * w1.x + xv.y * w1.y + xv.z * w1.z + xv.w * w1.w;
            }
        }
        __syncthreads();
    }
    #pragma unroll
    for (int r = 0; r < 4; r++) {
        int m = m0 + tm * 4 + r;
        if (m < TOT_N) {
            g_fcp[(kb * TOT_N + m) * 64 + tn     ] = acc[r][0];
            g_fcp[(kb * TOT_N + m) * 64 + tn + 32] = acc[r][1];
        }
    }
}

// reduce K-split partials + bias -> g_item
__global__ void k_fcred(const float* __restrict__ b) {
    int idx = blockIdx.x * blockDim.x + threadIdx.x;
    if (idx >= TOT_N * 64) return;
    float s = b[idx & 63];
    #pragma unroll
    for (int kb = 0; kb < KSPLIT; kb++) s += g_fcp[kb * TOT_N * 64 + idx];
    g_item[idx] = s;
}

// ---------------- standardize per feature over a group (ddof=1) ----------------
// grid = 2 (block 0: cells, block 1: drugs), block = 256
__global__ void k_std() {
    int base = blockIdx.x ? CELL_N * 64 : 0;
    int N    = blockIdx.x ? DRUG_N : CELL_N;
    __shared__ float red[256];
    __shared__ float mv[64];
    __shared__ float sv[64];
    float* x = g_item + base;
    int tid = threadIdx.x;
    int j = tid & 63, q = tid >> 6;
    float s = 0.f;
    for (int n = q; n < N; n += 4) s += x[n * 64 + j];
    red[tid] = s;
    __syncthreads();
    if (tid < 64) mv[tid] = (red[tid] + red[tid + 64] + red[tid + 128] + red[tid + 192]) / (float)N;
    __syncthreads();
    float mean = mv[j];
    float ss = 0.f;
    for (int n = q; n < N; n += 4) { float d = x[n * 64 + j] - mean; ss += d * d; }
    __syncthreads();
    red[tid] = ss;
    __syncthreads();
    if (tid < 64) {
        float var = (red[tid] + red[tid + 64] + red[tid + 128] + red[tid + 192]) / (float)(N - 1);
        sv[tid] = rsqrtf(var);
    }
    __syncthreads();
    float inv = sv[j];
    for (int n = q; n < N; n += 4) x[n * 64 + j] = (x[n * 64 + j] - mean) * inv;
}

// ---------------- interact: attention over 128 gathered protein rows ----------------
// grid = N*2 (one block per (n, hop)), block = 128
__global__ void k_interact(const int* __restrict__ nbr, const float* __restrict__ table,
                           int item_base, int inter_base) {
    int nh = blockIdx.x;
    int n = nh >> 1, h = nh & 1;
    __shared__ float rows[128 * 65];   // padded: conflict-free both ways
    __shared__ float it[64];
    __shared__ int   idxs[128];
    __shared__ float sc[128];
    __shared__ float tmp[128];
    int tid = threadIdx.x;
    idxs[tid] = nbr[nh * 128 + tid];
    if (tid < 64) it[tid] = g_item[item_base + n * 64 + tid];
    __syncthreads();
    for (int e = tid; e < 128 * 64; e += 128) {
        int k = e >> 6, d = e & 63;
        rows[k * 65 + d] = table[idxs[k] * 64 + d];
    }
    __syncthreads();
    float s = 0.f;
    #pragma unroll 8
    for (int d = 0; d < 64; d++) s += rows[tid * 65 + d] * it[d];
    tmp[tid] = s;
    __syncthreads();
    #pragma unroll
    for (int off = 64; off; off >>= 1) {
        if (tid < off) tmp[tid] = fmaxf(tmp[tid], tmp[tid + off]);
        __syncthreads();
    }
    float mx = tmp[0];
    __syncthreads();
    float e = expf(s - mx);
    sc[tid] = e;
    tmp[tid] = e;
    __syncthreads();
    #pragma unroll
    for (int off = 64; off; off >>= 1) {
        if (tid < off) tmp[tid] += tmp[tid + off];
        __syncthreads();
    }
    float inv = 1.f / tmp[0];
    if (tid < 64) {
        float o = 0.f;
        #pragma unroll 8
        for (int k = 0; k < 128; k++) o += sc[k] * rows[k * 65 + tid];
        g_inter[inter_base + n * 128 + h * 64 + tid] = o * inv;
    }
}

// ---------------- agg: emb[n,j] = inter[n,:] . agg_w[j,:] + b[j]; also |emb|^2 ----------------
// grid = TOT_N, block = 128
__global__ void k_agg(const float* __restrict__ W, const float* __restrict__ b) {
    int n = blockIdx.x;
    __shared__ float xr[128];
    __shared__ float red[64];
    int tid = threadIdx.x;
    xr[tid] = g_inter[n * 128 + tid];
    __syncthreads();
    float e = 0.f;
    if (tid < 64) {
        float s = b[tid];
        #pragma unroll 8
        for (int t = 0; t < 128; t++) s += W[tid * 128 + t] * xr[t];
        g_emb[n * 64 + tid] = s;
        e = s * s;
    }
    if (tid < 64) red[tid] = e;
    __syncthreads();
    if (tid < 32) {
        float v = red[tid] + red[tid + 32];
        #pragma unroll
        for (int o = 16; o; o >>= 1) v += __shfl_down_sync(0xffffffffu, v, o);
        if (tid == 0) g_normsq[n] = v;
    }
}

// ---------------- U[c,t] = sum_j comb_w[j,t] * cell_emb[c,j] ----------------
// grid = CELL_N, block = 128
__global__ void k_u(const float* __restrict__ combw) {
    int c = blockIdx.x;
    __shared__ float e[64];
    int tid = threadIdx.x;
    if (tid < 64) e[tid] = g_emb[c * 64 + tid];
    __syncthreads();
    float s = 0.f;
    #pragma unroll 8
    for (int j = 0; j < 64; j++) s += combw[j * 128 + tid] * e[j];
    g_U[c * 128 + tid] = s;
}

// ---------------- per-batch score + item_reg partials (deterministic) ----------------
// grid = 32, block = 128
__global__ void k_score(const int* __restrict__ data, float* __restrict__ out) {
    int bidx = blockIdx.x * blockDim.x + threadIdx.x;
    float reg = 0.f;
    if (bidx < BATCH) {
        int c  = data[3 * bidx];
        int d1 = data[3 * bidx + 1];
        int d2 = data[3 * bidx + 2];
        const float* e1 = g_emb + (CELL_N + d1) * 64;
        const float* e2 = g_emb + (CELL_N + d2) * 64;
        const float* u  = g_U + c * 128;
        float s = 0.f;
        #pragma unroll 8
        for (int t = 0; t < 64; t++) {
            float a = e1[t], bb = e2[t];
            s += a * u[t] + bb * u[64 + t] - a * bb;
        }
        out[bidx] = s;
        reg = 0.5f * (g_normsq[c] + g_normsq[CELL_N + d1] + g_normsq[CELL_N + d2]);
    }
    __shared__ float red[128];
    red[threadIdx.x] = reg;
    __syncthreads();
    #pragma unroll
    for (int off = 64; off; off >>= 1) {
        if (threadIdx.x < off) red[threadIdx.x] += red[threadIdx.x + off];
        __syncthreads();
    }
    if (threadIdx.x == 0) g_part[blockIdx.x] = red[0];
}

// ---------------- node_reg (only batch rows 0 and 1 index the hop axis) + loss ----------------
// grid = 1, block = 256
__global__ void k_loss(const int* __restrict__ data, const int* __restrict__ cell_nbr,
                       const int* __restrict__ drug_nbr, float* __restrict__ out, int loss_idx) {
    __shared__ float red[256];
    int tid = threadIdx.x;
    float s = 0.f;
    for (int e = tid; e < 1536; e += 256) {
        int set = e >> 8, off = e & 255;
        int hop = set / 3, which = set - hop * 3;
        int nodeidx = data[hop * 3 + which];
        int p = (which == 0) ? cell_nbr[nodeidx * 256 + off] : drug_nbr[nodeidx * 256 + off];
        s += g_tablesq[p];
    }
    red[tid] = s;
    __syncthreads();
    #pragma unroll
    for (int off = 128; off; off >>= 1) {
        if (tid < off) red[tid] += red[tid + off];
        __syncthreads();
    }
    if (tid == 0) {
        float item_reg = 0.f;
        #pragma unroll
        for (int i = 0; i < 32; i++) item_reg += g_part[i];
        out[loss_idx] = 1e-6f * (item_reg + 0.5f * red[0]) / (float)BATCH;
    }
}

// ---------------- launch ----------------
extern "C" void kernel_launch(void* const* d_in, const int* in_sizes, int n_in,
                              void* d_out, int out_size) {
    const int*   data     = (const int*)  d_in[0];
    const int*   cell_nbr = (const int*)  d_in[1];
    const int*   drug_nbr = (const int*)  d_in[2];
    const float* table    = (const float*)d_in[3];
    const float* cell_pre = (const float*)d_in[4];
    const float* drug_pre = (const float*)d_in[5];
    const float* c1w      = (const float*)d_in[6];
    const float* c1b      = (const float*)d_in[7];
    const float* c2w      = (const float*)d_in[8];
    const float* c2b      = (const float*)d_in[9];
    const float* ow       = (const float*)d_in[10];
    const float* ob       = (const float*)d_in[11];
    const float* aw       = (const float*)d_in[12];
    const float* ab       = (const float*)d_in[13];
    const float* cw       = (const float*)d_in[14];
    float* out = (float*)d_out;

    k_tablesq<<<(NPROT * 32 + 255) / 256, 256>>>(table);

    k_conv1<<<CELL_N * 2, 256>>>(cell_pre, c1w, c1b, 0);
    k_conv1<<<DRUG_N * 2, 256>>>(drug_pre, c1w, c1b, CELL_N * 4 * 64 * 64);
    k_conv2<<<TOT_N * 2, 256>>>(c2w, c2b);

    dim3 fcg(27, KSPLIT);
    k_fc<<<fcg, 256>>>(ow);
    k_fcred<<<(TOT_N * 64 + 255) / 256, 256>>>(ob);

    k_std<<<2, 256>>>();

    k_interact<<<CELL_N * 2, 128>>>(cell_nbr, table, 0, 0);
    k_interact<<<DRUG_N * 2, 128>>>(drug_nbr, table, CELL_N * 64, CELL_N * 128);

    k_agg<<<TOT_N, 128>>>(aw, ab);
    k_u<<<CELL_N, 128>>>(cw);
    k_score<<<32, 128>>>(data, out);
    k_loss<<<1, 256>>>(data, cell_nbr, drug_nbr, out, out_size - 1);
}